// round 17
// baseline (speedup 1.0000x reference)
#include <cuda_runtime.h>
#include <cuda_bf16.h>
#include <cuda_fp16.h>
#include <stdint.h>

#define BHW   4096
#define CCH   256
#define NBAT  4
#define NTOK  16384
#define NGRP  32
#define GELEMS (8*BHW)
#define OUT_MAIN ((size_t)NBAT*CCH*BHW)

#define FITERS 64
// flash smem BYTE offsets (BN=64)
#define KB(i)  ((i)*33792)
#define VB(j)  (67584 + (j)*33792)
#define PB(p)  (169344 + (p)*10240)
#define SLB    189824
#define QSTGB  67584
#define FSMEM  190080

__device__ __half   g_th[(size_t)NTOK*CCH];
__device__ __half   g_qkh[(size_t)NTOK*512];
__device__ unsigned g_vp[(size_t)(NTOK/2)*256];
__device__ __half   g_oh[(size_t)NTOK*CCH];
__device__ __half   g_wh[(size_t)1024*256];
__device__ float    g_ps[512*2];

__device__ __forceinline__ unsigned fu(float f) { return __float_as_uint(f); }
__device__ __forceinline__ void mma_f16(float* c, const unsigned* a, unsigned b0, unsigned b1) {
    asm volatile("mma.sync.aligned.m16n8k16.row.col.f32.f16.f16.f32 "
                 "{%0,%1,%2,%3}, {%4,%5,%6,%7}, {%8,%9}, {%0,%1,%2,%3};"
                 : "+f"(c[0]), "+f"(c[1]), "+f"(c[2]), "+f"(c[3])
                 : "r"(a[0]), "r"(a[1]), "r"(a[2]), "r"(a[3]), "r"(b0), "r"(b1));
}
__device__ __forceinline__ void mma_bf16(float* c, const unsigned* a, unsigned b0, unsigned b1) {
    asm volatile("mma.sync.aligned.m16n8k16.row.col.f32.bf16.bf16.f32 "
                 "{%0,%1,%2,%3}, {%4,%5,%6,%7}, {%8,%9}, {%0,%1,%2,%3};"
                 : "+f"(c[0]), "+f"(c[1]), "+f"(c[2]), "+f"(c[3])
                 : "r"(a[0]), "r"(a[1]), "r"(a[2]), "r"(a[3]), "r"(b0), "r"(b1));
}
__device__ __forceinline__ uint32_t smem_u32(const void* p) {
    uint32_t a;
    asm("{ .reg .u64 t; cvta.to.shared.u64 t, %1; cvt.u32.u64 %0, t; }" : "=r"(a) : "l"(p));
    return a;
}
__device__ __forceinline__ void cp16(uint32_t saddr, const void* g) {
    asm volatile("cp.async.cg.shared.global [%0], [%1], 16;" :: "r"(saddr), "l"(g));
}
#define CP_COMMIT asm volatile("cp.async.commit_group;" ::: "memory")
#define CP_WAIT0  asm volatile("cp.async.wait_group 0;" ::: "memory")
__device__ __forceinline__ unsigned pack_bf(float lo, float hi) {
    unsigned r;
    asm("cvt.rn.bf16x2.f32 %0, %1, %2;" : "=r"(r) : "f"(hi), "f"(lo));
    return r;
}

// ------- prep: w_pack (blocks 0..1023) + gn_stats1 (blocks 1024..1535) -------
__global__ void prep(const float* __restrict__ wq, const float* __restrict__ wk,
                     const float* __restrict__ wv, const float* __restrict__ wp,
                     const float* __restrict__ x) {
    if (blockIdx.x < 1024) {
        int r = blockIdx.x, tid = threadIdx.x;
        const float* w = (r < 256) ? wq : (r < 512) ? wk : (r < 768) ? wv : wp;
        g_wh[(size_t)r * 256 + tid] = __float2half(w[(size_t)(r & 255) * 256 + tid]);
        return;
    }
    int cta = blockIdx.x - 1024;
    const float4* p = (const float4*)(x + (size_t)cta * 8192);
    float s = 0.f, ss = 0.f;
    for (int i = threadIdx.x; i < 2048; i += 256) {
        float4 v = p[i];
        s += v.x + v.y + v.z + v.w;
        ss += v.x*v.x + v.y*v.y + v.z*v.z + v.w*v.w;
    }
    __shared__ float rs[8], rss[8];
    #pragma unroll
    for (int o = 16; o; o >>= 1) { s += __shfl_down_sync(~0u, s, o); ss += __shfl_down_sync(~0u, ss, o); }
    if ((threadIdx.x & 31) == 0) { rs[threadIdx.x >> 5] = s; rss[threadIdx.x >> 5] = ss; }
    __syncthreads();
    if (threadIdx.x < 32) {
        s  = (threadIdx.x < 8) ? rs[threadIdx.x]  : 0.f;
        ss = (threadIdx.x < 8) ? rss[threadIdx.x] : 0.f;
        #pragma unroll
        for (int o = 4; o; o >>= 1) { s += __shfl_down_sync(~0u, s, o); ss += __shfl_down_sync(~0u, ss, o); }
        if (threadIdx.x == 0) { g_ps[cta*2] = s; g_ps[cta*2 + 1] = ss; }
    }
}

// ---------------- gn_apply (stats finalize inline) ---------------------------
__global__ void gn_apply(const float* __restrict__ x, const float* __restrict__ gamma,
                         const float* __restrict__ beta) {
    __shared__ float tile[32][33];
    __shared__ float smu[4], srs[4];
    int b = blockIdx.z, c0 = blockIdx.y * 32, s0 = blockIdx.x * 32;
    int tx = threadIdx.x, ty = threadIdx.y;
    int tid = ty * 32 + tx;
    if (tid < 4) {
        int bg = b * NGRP + (c0 >> 3) + tid;
        float s = 0.f, ss = 0.f;
        #pragma unroll
        for (int j = 0; j < 4; j++) { s += g_ps[(bg*4 + j)*2]; ss += g_ps[(bg*4 + j)*2 + 1]; }
        float mu = s / (float)GELEMS;
        float var = ss / (float)GELEMS - mu * mu;
        smu[tid] = mu; srs[tid] = rsqrtf(var + 1e-6f);
    }
    __syncthreads();
    for (int i = ty; i < 32; i += 8) {
        int c = c0 + i;
        float v = x[((size_t)(b * CCH + c)) * BHW + s0 + tx];
        tile[i][tx] = (v - smu[i >> 3]) * srs[i >> 3] * gamma[c] + beta[c];
    }
    __syncthreads();
    for (int i = ty; i < 32; i += 8)
        g_th[((size_t)(b * BHW + s0 + i)) * CCH + c0 + tx] = __float2half(tile[tx][i]);
}

// --------- fp16 gemm core, cp.async double-buffered (K=256) ------------------
__device__ __forceinline__ void gemm_core_h(const __half* A, const __half* B, int m0,
                                            __half* As, __half* Bs, float acc[2][8][4]) {
    const int tid = threadIdx.x, lane = tid & 31, warp = tid >> 5;
    const int wm = warp >> 1, wn = warp & 1, g = lane >> 2, t4 = lane & 3;
    uint32_t sa = smem_u32(As), sbb = smem_u32(Bs);
    #pragma unroll
    for (int mi = 0; mi < 2; mi++)
        #pragma unroll
        for (int ni = 0; ni < 8; ni++)
            #pragma unroll
            for (int e = 0; e < 4; e++) acc[mi][ni][e] = 0.f;
    #pragma unroll
    for (int it = 0; it < 2; it++) {
        int i = tid + it * 256, row = i >> 2, seg = i & 3;
        cp16(sa  + row * 80 + seg * 16, A + (size_t)(m0 + row) * 256 + seg * 8);
        cp16(sbb + row * 80 + seg * 16, B + (size_t)row * 256 + seg * 8);
    }
    CP_COMMIT;
    for (int kc8 = 0; kc8 < 8; kc8++) {
        CP_WAIT0; __syncthreads();
        if (kc8 + 1 < 8) {
            int kc = (kc8 + 1) * 32, buf = ((kc8 + 1) & 1) * 10240;
            #pragma unroll
            for (int it = 0; it < 2; it++) {
                int i = tid + it * 256, row = i >> 2, seg = i & 3;
                cp16(sa  + buf + row * 80 + seg * 16, A + (size_t)(m0 + row) * 256 + kc + seg * 8);
                cp16(sbb + buf + row * 80 + seg * 16, B + (size_t)row * 256 + kc + seg * 8);
            }
            CP_COMMIT;
        }
        const __half* Ab = As + (kc8 & 1) * 5120;
        const __half* Bb = Bs + (kc8 & 1) * 5120;
        #pragma unroll
        for (int k16 = 0; k16 < 2; k16++) {
            unsigned af[2][4];
            #pragma unroll
            for (int mi = 0; mi < 2; mi++) {
                int r = wm * 32 + mi * 16 + g;
                af[mi][0] = *(unsigned*)&Ab[r * 40 + k16*16 + t4*2];
                af[mi][1] = *(unsigned*)&Ab[(r + 8) * 40 + k16*16 + t4*2];
                af[mi][2] = *(unsigned*)&Ab[r * 40 + k16*16 + 8 + t4*2];
                af[mi][3] = *(unsigned*)&Ab[(r + 8) * 40 + k16*16 + 8 + t4*2];
            }
            #pragma unroll
            for (int ni = 0; ni < 8; ni++) {
                int cc = wn * 64 + ni * 8 + g;
                unsigned b0 = *(unsigned*)&Bb[cc * 40 + k16*16 + t4*2];
                unsigned b1 = *(unsigned*)&Bb[cc * 40 + k16*16 + 8 + t4*2];
                mma_f16(acc[0][ni], af[0], b0, b1);
                mma_f16(acc[1][ni], af[1], b0, b1);
            }
        }
    }
}

// qkv (+inline u for K CTAs): q,k fp16 (k scaled u/16); v bf16 pair-packed
__global__ __launch_bounds__(256, 2)
void gemm_qkv(const float* __restrict__ bq, const float* __restrict__ bk,
              const float* __restrict__ bv, const float* __restrict__ wu,
              const float* __restrict__ bu, float* __restrict__ dout_u) {
    const int n0 = blockIdx.x * 128, m0 = blockIdx.y * 128;
    const float* Bi = (n0 < 256) ? bq : (n0 < 512) ? bk : bv;
    __shared__ __align__(16) __half As[2 * 5120];
    __shared__ __align__(16) __half Bs[2 * 5120];
    __shared__ float su[128];
    const int tid = threadIdx.x, lane = tid & 31, warp = tid >> 5;

    if (n0 >= 256 && n0 < 512) {     // inline u = sigmoid(t . wu + bu)
        int row = warp * 16 + (lane >> 1);        // 8 warps x 16 rows
        int half0 = (lane & 1) * 64;
        const __half2* t2 = (const __half2*)(g_th + (size_t)(m0 + row) * 256);
        float s = 0.f;
        #pragma unroll
        for (int j = 0; j < 64; j++) {
            float2 f = __half22float2(t2[half0 + j]);
            s += f.x * wu[(half0 + j) * 2] + f.y * wu[(half0 + j) * 2 + 1];
        }
        s += __shfl_xor_sync(~0u, s, 1);
        if ((lane & 1) == 0) su[row] = 1.f / (1.f + expf(-(s + bu[0])));
    }
    // (first CP_WAIT0/__syncthreads inside core orders su before epilogue)
    float acc[2][8][4];
    gemm_core_h(g_th, g_wh + (size_t)n0 * 256, m0, As, Bs, acc);

    const int wm = warp >> 1, wn = warp & 1, g = lane >> 2, t4 = lane & 3;
    #pragma unroll
    for (int mi = 0; mi < 2; mi++) {
        int rbase = m0 + wm * 32 + mi * 16 + g;
        #pragma unroll
        for (int ni = 0; ni < 8; ni++) {
            int cl = wn * 64 + ni * 8 + t4 * 2, cg = n0 + cl;
            #pragma unroll
            for (int half = 0; half < 2; half++) {
                int rr = rbase + half * 8;
                float v0 = acc[mi][ni][half * 2 + 0] + Bi[(n0 & 255) + cl];
                float v1 = acc[mi][ni][half * 2 + 1] + Bi[(n0 & 255) + cl + 1];
                if (cg < 512) {
                    if (cg >= 256) { float us = su[rr - m0] * 0.0625f; v0 *= us; v1 *= us; }
                    *(__half2*)&g_qkh[(size_t)rr * 512 + cg] = __floats2half2_rn(v0, v1);
                } else {
                    int c2 = cg - 512, t2 = rr >> 1, par = rr & 1;
                    __nv_bfloat16* vb = (__nv_bfloat16*)g_vp;
                    vb[((size_t)t2 * 256 + c2) * 2 + par]     = __float2bfloat16(v0);
                    vb[((size_t)t2 * 256 + c2 + 1) * 2 + par] = __float2bfloat16(v1);
                }
            }
        }
    }
    if (n0 == 256 && tid < 128) dout_u[m0 + tid] = su[tid];
}

// proj transposed: out[b][c][s] = x + Wp @ O^T + bp
__global__ __launch_bounds__(256, 2)
void gemm_proj_t(const float* __restrict__ x, const float* __restrict__ bias,
                 float* __restrict__ out) {
    const int n0 = blockIdx.x * 128;
    const int m0 = blockIdx.y * 128;
    __shared__ __align__(16) __half As[2 * 5120];
    __shared__ __align__(16) __half Bs[2 * 5120];
    float acc[2][8][4];
    gemm_core_h(g_wh + (size_t)768 * 256, g_oh + (size_t)n0 * 256, m0, As, Bs, acc);
    const int lane = threadIdx.x & 31, warp = threadIdx.x >> 5;
    const int wm = warp >> 1, wn = warp & 1, g = lane >> 2, t4 = lane & 3;
    #pragma unroll
    for (int mi = 0; mi < 2; mi++) {
        int chb = m0 + wm * 32 + mi * 16 + g;
        #pragma unroll
        for (int ni = 0; ni < 8; ni++) {
            int tok = n0 + wn * 64 + ni * 8 + t4 * 2;
            int bb = tok >> 12, s = tok & 4095;
            #pragma unroll
            for (int half = 0; half < 2; half++) {
                int ch = chb + half * 8;
                size_t idx = ((size_t)(bb * CCH + ch)) * BHW + s;
                float2 xv = *(const float2*)(x + idx);
                *(float2*)(out + idx) =
                    make_float2(acc[mi][ni][half * 2 + 0] + bias[ch] + xv.x,
                                acc[mi][ni][half * 2 + 1] + bias[ch] + xv.y);
            }
        }
    }
}

// -------- flash7: BN=64, 16 warps = 4 QK + 8 PV + 4 loaders ------------------
__global__ __launch_bounds__(512, 1)
void flash7(float* __restrict__ unused) {
    extern __shared__ __align__(16) char dsmb[];
    float* dsm = (float*)dsmb;
    uint32_t sb = smem_u32(dsmb);
    int b = blockIdx.y, q0 = blockIdx.x * 64;
    int tid = threadIdx.x, lane = tid & 31, warp = tid >> 5;
    int g = lane >> 2, t4 = lane & 3;
    size_t tokb = (size_t)b * BHW;
    const __half* Qg = g_qkh + (tokb + q0) * 512;
    const __half* Kg = g_qkh + tokb * 512 + 256;
    const unsigned* Vg = g_vp + (size_t)b * 2048 * 256;

    for (int i = tid; i < 2048; i += 512) {
        int r = i >> 5, c8 = i & 31;
        cp16(sb + QSTGB + r * 528 + c8 * 16, Qg + (size_t)r * 512 + c8 * 8);
    }
    CP_COMMIT; CP_WAIT0; __syncthreads();

    float rp[64];
    if (warp < 4) {
        int r0 = warp * 16 + g;
        const __half* q = (const __half*)(dsmb + QSTGB);
        #pragma unroll
        for (int k16 = 0; k16 < 16; k16++) {
            rp[k16*4+0] = __uint_as_float(*(const unsigned*)&q[r0 * 264 + k16*16 + t4*2]);
            rp[k16*4+1] = __uint_as_float(*(const unsigned*)&q[(r0+8) * 264 + k16*16 + t4*2]);
            rp[k16*4+2] = __uint_as_float(*(const unsigned*)&q[r0 * 264 + k16*16 + 8 + t4*2]);
            rp[k16*4+3] = __uint_as_float(*(const unsigned*)&q[(r0+8) * 264 + k16*16 + 8 + t4*2]);
        }
    } else {
        #pragma unroll
        for (int j = 0; j < 64; j++) rp[j] = 0.f;
    }
    __syncthreads();

    for (int i = tid; i < 2048; i += 512) {
        int r = i >> 5, c8 = i & 31;
        cp16(sb + KB(0) + r * 528 + c8 * 16, Kg + (size_t)r * 512 + c8 * 8);
    }
    for (int i = tid; i < 2048; i += 512) {
        int r = i >> 6, c4 = (i & 63) * 4;
        cp16(sb + VB(0) + r * 1056 + c4 * 4, Vg + (size_t)r * 256 + c4);
    }
    CP_COMMIT;

    int pw = warp - 4, wm = pw & 3, wn = pw >> 2;
    float lac0 = 0.f, lac1 = 0.f;

    for (int it = 0; it <= FITERS; ++it) {
        CP_WAIT0; __syncthreads();
        if (warp >= 12) {
            if (it + 1 < FITERS) {
                int t2 = tid - 384;
                const __half* kn = Kg + (size_t)(it + 1) * 64 * 512;
                const unsigned* vn = Vg + (size_t)(it + 1) * 32 * 256;
                uint32_t kd = sb + KB((it + 1) & 1), vd = sb + VB((it + 1) % 3);
                for (int i = t2; i < 2048; i += 128) {
                    int r = i >> 5, c8 = i & 31;
                    cp16(kd + r * 528 + c8 * 16, kn + (size_t)r * 512 + c8 * 8);
                }
                for (int i = t2; i < 2048; i += 128) {
                    int r = i >> 6, c4 = (i & 63) * 4;
                    cp16(vd + r * 1056 + c4 * 4, vn + (size_t)r * 256 + c4);
                }
                CP_COMMIT;
            }
        } else if (warp < 4) {
            if (it < FITERS) {
                const __half* kb = (const __half*)(dsmb + KB(it & 1));
                float sacc[8][4];
                #pragma unroll
                for (int ni = 0; ni < 8; ni++)
                    #pragma unroll
                    for (int e = 0; e < 4; e++) sacc[ni][e] = 0.f;
                #pragma unroll
                for (int k16 = 0; k16 < 16; k16++) {
                    unsigned af[4] = { fu(rp[k16*4]), fu(rp[k16*4+1]), fu(rp[k16*4+2]), fu(rp[k16*4+3]) };
                    #pragma unroll
                    for (int ni = 0; ni < 8; ni++) {
                        int c = ni * 8 + g;
                        unsigned b0 = *(const unsigned*)&kb[c * 264 + k16*16 + t4*2];
                        unsigned b1 = *(const unsigned*)&kb[c * 264 + k16*16 + 8 + t4*2];
                        mma_f16(sacc[ni], af, b0, b1);
                    }
                }
                unsigned* P = (unsigned*)(dsmb + PB(it & 1));
                int r0 = warp * 16 + g;
                #pragma unroll
                for (int ni = 0; ni < 8; ni++) {
                    float e0 = __expf(sacc[ni][0]), e1 = __expf(sacc[ni][1]);
                    float e2 = __expf(sacc[ni][2]), e3 = __expf(sacc[ni][3]);
                    lac0 += e0 + e1; lac1 += e2 + e3;
                    P[r0 * 40 + ni*4 + t4]       = pack_bf(e0, e1);
                    P[(r0 + 8) * 40 + ni*4 + t4] = pack_bf(e2, e3);
                }
            }
        } else {
            if (it >= 1) {
                int pit = it - 1;
                const unsigned* P = (const unsigned*)(dsmb + PB(pit & 1));
                const unsigned* V = (const unsigned*)(dsmb + VB(pit % 3));
                int m0 = wm * 16;
                #pragma unroll
                for (int k16 = 0; k16 < 4; k16++) {
                    unsigned a[4] = {
                        P[(m0 + g) * 40 + k16*8 + t4],
                        P[(m0 + 8 + g) * 40 + k16*8 + t4],
                        P[(m0 + g) * 40 + k16*8 + 4 + t4],
                        P[(m0 + 8 + g) * 40 + k16*8 + 4 + t4] };
                    #pragma unroll
                    for (int ni = 0; ni < 16; ni++) {
                        int c = wn * 128 + ni * 8 + g;
                        unsigned b0 = V[(k16*8 + t4) * 264 + c];
                        unsigned b1 = V[(k16*8 + 4 + t4) * 264 + c];
                        mma_bf16(&rp[ni*4], a, b0, b1);
                    }
                }
            }
        }
    }

    if (warp < 4) {
        lac0 += __shfl_xor_sync(~0u, lac0, 1);
        lac0 += __shfl_xor_sync(~0u, lac0, 2);
        lac1 += __shfl_xor_sync(~0u, lac1, 1);
        lac1 += __shfl_xor_sync(~0u, lac1, 2);
        if (t4 == 0) {
            dsm[SLB/4 + warp*16 + g]     = lac0;
            dsm[SLB/4 + warp*16 + g + 8] = lac1;
        }
    }
    __syncthreads();
    if (warp >= 4 && warp < 12) {
        int r = wm * 16 + g;
        float i0 = 1.f / dsm[SLB/4 + r];
        float i1 = 1.f / dsm[SLB/4 + r + 8];
        __half* o0 = g_oh + (tokb + q0 + r) * 256;
        __half* o1 = g_oh + (tokb + q0 + r + 8) * 256;
        #pragma unroll
        for (int ni = 0; ni < 16; ni++) {
            int cc = wn * 128 + ni * 8 + t4 * 2;
            *(__half2*)&o0[cc] = __floats2half2_rn(rp[ni*4] * i0,   rp[ni*4+1] * i0);
            *(__half2*)&o1[cc] = __floats2half2_rn(rp[ni*4+2] * i1, rp[ni*4+3] * i1);
        }
    }
    (void)unused;
}

// ---------------- launch -----------------------------------------------------
extern "C" void kernel_launch(void* const* d_in, const int* in_sizes, int n_in,
                              void* d_out, int out_size) {
    (void)in_sizes; (void)n_in; (void)out_size;
    const float* x     = (const float*)d_in[0];
    const float* gamma = (const float*)d_in[1];
    const float* beta  = (const float*)d_in[2];
    const float* wq = (const float*)d_in[3],  *bq = (const float*)d_in[4];
    const float* wk = (const float*)d_in[5],  *bk = (const float*)d_in[6];
    const float* wv = (const float*)d_in[7],  *bv = (const float*)d_in[8];
    const float* wu = (const float*)d_in[9],  *bu = (const float*)d_in[10];
    const float* wp = (const float*)d_in[11], *bp = (const float*)d_in[12];
    float* out = (float*)d_out;

    cudaFuncSetAttribute(flash7, cudaFuncAttributeMaxDynamicSharedMemorySize, FSMEM);

    prep<<<1536, 256>>>(wq, wk, wv, wp, x);
    gn_apply<<<dim3(BHW / 32, CCH / 32, NBAT), dim3(32, 8)>>>(x, gamma, beta);
    gemm_qkv<<<dim3(6, 128), 256>>>(bq, bk, bv, wu, bu, out + OUT_MAIN);
    flash7<<<dim3(BHW / 64, NBAT), 512, FSMEM>>>(out);
    gemm_proj_t<<<dim3(128, 2), 256>>>(x, bp, out);
}